// round 11
// baseline (speedup 1.0000x reference)
#include <cuda_runtime.h>
#include <cuda_fp16.h>
#include <stdint.h>
#include <math.h>

#define N_HEAD 50000
#define N_TAIL 50000
#define NE     800000
#define F_IN   256
#define DH     64
#define NH     4
#define HD     256   // NH*DH
#define FEW    64
#define N_ETYPES 5
#define NEG_SLOPE 0.2f
#define SCAN_B 1024
#define NSCAN ((N_HEAD + SCAN_B - 1) / SCAN_B)   // 49

// ---------------- device scratch ----------------
__device__ __half g_h_tail[N_TAIL * HD];    // 25.6 MB (fp16)
__device__ float g_hl[N_HEAD * NH];
__device__ float g_hr[N_TAIL * NH];
__device__ float g_Wal[F_IN * NH];
__device__ float g_War[F_IN * NH];
__device__ float g_he[N_ETYPES * NH];
__device__ int   g_counts[N_HEAD + 1];
__device__ int   g_offsets[N_HEAD + 1];
__device__ int   g_cursor[N_HEAD];
__device__ int   g_bsum[NSCAN];
__device__ unsigned g_packed[NE];           // tail | (etype<<20)

// ---------------- prep: zero counters + tiny weight folds ----------------
__global__ void k_prep(const float* __restrict__ W, const float* __restrict__ We,
                       const float* __restrict__ emb, const float* __restrict__ al,
                       const float* __restrict__ ar, const float* __restrict__ ae) {
    int gid = blockIdx.x * blockDim.x + threadIdx.x;
    if (gid <= N_HEAD) g_counts[gid] = 0;
    if (blockIdx.x != 0) return;

    __shared__ float M[FEW * NH];
    int t = threadIdx.x;  // 256
    for (int idx = t; idx < F_IN * NH; idx += 256) {
        int f = idx >> 2, h = idx & 3;
        float sl = 0.f, sr = 0.f;
        #pragma unroll 4
        for (int d = 0; d < DH; d++) {
            float w = W[f * HD + h * DH + d];
            sl += w * al[h * DH + d];
            sr += w * ar[h * DH + d];
        }
        g_Wal[idx] = sl;
        g_War[idx] = sr;
    }
    {
        int k = t >> 2, h = t & 3;
        float s = 0.f;
        #pragma unroll 4
        for (int f = 0; f < FEW; f++) s += ae[h * DH + f] * We[k * (FEW * NH) + h * FEW + f];
        M[t] = s;
    }
    __syncthreads();
    if (t < N_ETYPES * NH) {
        int ty = t >> 2, h = t & 3;
        float s = 0.f;
        #pragma unroll 4
        for (int k = 0; k < FEW; k++) s += emb[ty * FEW + k] * M[k * 4 + h];
        g_he[t] = s;
    }
}

// ---------------- hl / hr : rank-4 projections, warp per node ----------------
__global__ void k_hlhr(const float* __restrict__ hf, const float* __restrict__ tf) {
    __shared__ float sWal[F_IN * NH];
    __shared__ float sWar[F_IN * NH];
    int t = threadIdx.x;
    for (int i = t; i < F_IN * NH; i += 256) { sWal[i] = g_Wal[i]; sWar[i] = g_War[i]; }
    __syncthreads();
    int warp = t >> 5, lane = t & 31;
    int n = blockIdx.x * 8 + warp;
    if (n >= N_HEAD) return;
    int c0 = lane * 8;

    {
        const float4* fr = (const float4*)(hf + (size_t)n * F_IN + c0);
        float4 f0 = fr[0], f1 = fr[1];
        float fv[8] = {f0.x, f0.y, f0.z, f0.w, f1.x, f1.y, f1.z, f1.w};
        float s0 = 0.f, s1 = 0.f, s2 = 0.f, s3 = 0.f;
        #pragma unroll
        for (int j = 0; j < 8; j++) {
            const float* w = &sWal[(c0 + j) * 4];
            s0 += fv[j] * w[0]; s1 += fv[j] * w[1]; s2 += fv[j] * w[2]; s3 += fv[j] * w[3];
        }
        #pragma unroll
        for (int o = 16; o; o >>= 1) {
            s0 += __shfl_xor_sync(~0u, s0, o); s1 += __shfl_xor_sync(~0u, s1, o);
            s2 += __shfl_xor_sync(~0u, s2, o); s3 += __shfl_xor_sync(~0u, s3, o);
        }
        if (lane == 0) *(float4*)(g_hl + 4 * n) = make_float4(s0, s1, s2, s3);
    }
    {
        const float4* fr = (const float4*)(tf + (size_t)n * F_IN + c0);
        float4 f0 = fr[0], f1 = fr[1];
        float fv[8] = {f0.x, f0.y, f0.z, f0.w, f1.x, f1.y, f1.z, f1.w};
        float s0 = 0.f, s1 = 0.f, s2 = 0.f, s3 = 0.f;
        #pragma unroll
        for (int j = 0; j < 8; j++) {
            const float* w = &sWar[(c0 + j) * 4];
            s0 += fv[j] * w[0]; s1 += fv[j] * w[1]; s2 += fv[j] * w[2]; s3 += fv[j] * w[3];
        }
        #pragma unroll
        for (int o = 16; o; o >>= 1) {
            s0 += __shfl_xor_sync(~0u, s0, o); s1 += __shfl_xor_sync(~0u, s1, o);
            s2 += __shfl_xor_sync(~0u, s2, o); s3 += __shfl_xor_sync(~0u, s3, o);
        }
        if (lane == 0) *(float4*)(g_hr + 4 * n) = make_float4(s0, s1, s2, s3);
    }
}

// ---------------- GEMM via HMMA: g_h_tail = fp16(tail_feature @ W) ----------------
#define GM 64
#define APAD 24
#define BPAD 264

__device__ __forceinline__ uint32_t smem_u32(const void* p) {
    return (uint32_t)__cvta_generic_to_shared(p);
}

__global__ void __launch_bounds__(256) k_gemm_mma(const float* __restrict__ A,
                                                  const float* __restrict__ B) {
    __shared__ __half As[2][GM][APAD];
    __shared__ __half Bs[2][16][BPAD];
    int t = threadIdx.x;
    int warp = t >> 5, lane = t & 31;
    int m0 = blockIdx.x * GM;
    int warp_m = (warp & 1) * 32;
    int warp_n = (warp >> 1) * 64;

    float acc[2][8][4];
    #pragma unroll
    for (int i = 0; i < 2; i++)
        #pragma unroll
        for (int j = 0; j < 8; j++)
            #pragma unroll
            for (int k = 0; k < 4; k++) acc[i][j][k] = 0.f;

    auto load_tile = [&](int buf, int k0) {
        {
            int row = t >> 2, kc = (t & 3) * 4;
            float4 a = (m0 + row < N_TAIL)
                ? *(const float4*)(A + (size_t)(m0 + row) * F_IN + k0 + kc)
                : make_float4(0.f, 0.f, 0.f, 0.f);
            __half2* dst = (__half2*)&As[buf][row][kc];
            dst[0] = __floats2half2_rn(a.x, a.y);
            dst[1] = __floats2half2_rn(a.z, a.w);
        }
        #pragma unroll
        for (int j = 0; j < 4; j++) {
            int idx = t + j * 256;
            int br = idx >> 6, bc = (idx & 63) * 4;
            float4 b = *(const float4*)(B + (size_t)(k0 + br) * HD + bc);
            __half2* dst = (__half2*)&Bs[buf][br][bc];
            dst[0] = __floats2half2_rn(b.x, b.y);
            dst[1] = __floats2half2_rn(b.z, b.w);
        }
    };

    load_tile(0, 0);
    __syncthreads();

    int lm_r = lane & 15;
    int lm_c = (lane >> 4) * 8;

    for (int kc = 0; kc < F_IN / 16; kc++) {
        int buf = kc & 1;
        if (kc < F_IN / 16 - 1) load_tile(buf ^ 1, (kc + 1) * 16);

        uint32_t afr[2][4];
        #pragma unroll
        for (int mt = 0; mt < 2; mt++) {
            uint32_t addr = smem_u32(&As[buf][warp_m + mt * 16 + lm_r][lm_c]);
            asm volatile("ldmatrix.sync.aligned.m8n8.x4.shared.b16 {%0,%1,%2,%3},[%4];"
                         : "=r"(afr[mt][0]), "=r"(afr[mt][1]), "=r"(afr[mt][2]), "=r"(afr[mt][3])
                         : "r"(addr));
        }
        uint32_t bfr[4][4];
        #pragma unroll
        for (int ng = 0; ng < 4; ng++) {
            uint32_t addr = smem_u32(&Bs[buf][lm_r][warp_n + ng * 16 + lm_c]);
            asm volatile("ldmatrix.sync.aligned.m8n8.x4.trans.shared.b16 {%0,%1,%2,%3},[%4];"
                         : "=r"(bfr[ng][0]), "=r"(bfr[ng][1]), "=r"(bfr[ng][2]), "=r"(bfr[ng][3])
                         : "r"(addr));
        }
        #pragma unroll
        for (int mt = 0; mt < 2; mt++) {
            #pragma unroll
            for (int nt = 0; nt < 8; nt++) {
                uint32_t b0 = bfr[nt >> 1][(nt & 1) * 2];
                uint32_t b1 = bfr[nt >> 1][(nt & 1) * 2 + 1];
                asm volatile(
                    "mma.sync.aligned.m16n8k16.row.col.f32.f16.f16.f32 "
                    "{%0,%1,%2,%3},{%4,%5,%6,%7},{%8,%9},{%0,%1,%2,%3};"
                    : "+f"(acc[mt][nt][0]), "+f"(acc[mt][nt][1]),
                      "+f"(acc[mt][nt][2]), "+f"(acc[mt][nt][3])
                    : "r"(afr[mt][0]), "r"(afr[mt][1]), "r"(afr[mt][2]), "r"(afr[mt][3]),
                      "r"(b0), "r"(b1));
            }
        }
        __syncthreads();
    }

    int rbase = m0 + warp_m + (lane >> 2);
    int cbase = warp_n + (lane & 3) * 2;
    #pragma unroll
    for (int mt = 0; mt < 2; mt++) {
        int r0 = rbase + mt * 16;
        #pragma unroll
        for (int nt = 0; nt < 8; nt++) {
            int c = cbase + nt * 8;
            if (r0 < N_TAIL)
                *(__half2*)(g_h_tail + (size_t)r0 * HD + c) =
                    __floats2half2_rn(acc[mt][nt][0], acc[mt][nt][1]);
            if (r0 + 8 < N_TAIL)
                *(__half2*)(g_h_tail + (size_t)(r0 + 8) * HD + c) =
                    __floats2half2_rn(acc[mt][nt][2], acc[mt][nt][3]);
        }
    }
}

// ---------------- CSR build ----------------
__global__ void k_count(const int* __restrict__ edge_list) {
    int i = blockIdx.x * blockDim.x + threadIdx.x;
    if (i < NE) atomicAdd(&g_counts[edge_list[i]], 1);
}

__global__ void k_scan1() {
    __shared__ int warp_sums[32];
    int t = threadIdx.x, b = blockIdx.x;
    int idx = b * SCAN_B + t;
    int x = (idx < N_HEAD) ? g_counts[idx] : 0;
    int v = x;
    #pragma unroll
    for (int o = 1; o < 32; o <<= 1) {
        int u = __shfl_up_sync(~0u, v, o);
        if ((t & 31) >= o) v += u;
    }
    if ((t & 31) == 31) warp_sums[t >> 5] = v;
    __syncthreads();
    if (t < 32) {
        int w = warp_sums[t];
        #pragma unroll
        for (int o = 1; o < 32; o <<= 1) {
            int u = __shfl_up_sync(~0u, w, o);
            if (t >= o) w += u;
        }
        warp_sums[t] = w;
    }
    __syncthreads();
    int incl = v + ((t >= 32) ? warp_sums[(t >> 5) - 1] : 0);
    if (idx < N_HEAD) g_offsets[idx] = incl - x;
    if (t == SCAN_B - 1) g_bsum[b] = incl;
}

__global__ void k_scan2() {
    __shared__ int wsum[2];
    int t = threadIdx.x;  // 64
    int v = (t < NSCAN) ? g_bsum[t] : 0;
    int x = v;
    #pragma unroll
    for (int o = 1; o < 32; o <<= 1) {
        int u = __shfl_up_sync(~0u, x, o);
        if ((t & 31) >= o) x += u;
    }
    if ((t & 31) == 31) wsum[t >> 5] = x;
    __syncthreads();
    if (t >= 32) x += wsum[0];
    if (t < NSCAN) g_bsum[t] = x - v;
}

__global__ void k_scan3() {
    int t = threadIdx.x, b = blockIdx.x;
    int idx = b * SCAN_B + t;
    if (idx < N_HEAD) {
        int o = g_offsets[idx] + g_bsum[b];
        g_offsets[idx] = o;
        g_cursor[idx] = o;
    }
    if (idx == 0) g_offsets[N_HEAD] = NE;
}

__global__ void k_scatter(const int* __restrict__ edge_list, const int* __restrict__ tmp_edge) {
    int i = blockIdx.x * blockDim.x + threadIdx.x;
    if (i >= NE) return;
    int h  = edge_list[i];
    int tt = edge_list[NE + i];
    int ty = tmp_edge[i];
    int pos = atomicAdd(&g_cursor[h], 1);
    g_packed[pos] = (unsigned)tt | ((unsigned)ty << 20);
}

// ---------------- aggregation: warp per node, shfl-broadcast indices ----------------
__device__ __forceinline__ void acc_edge(float ex, uint4 u, float4& r0, float4& r1) {
    union { unsigned u; __half2 h; } c0, c1, c2, c3;
    c0.u = u.x; c1.u = u.y; c2.u = u.z; c3.u = u.w;
    float2 f0 = __half22float2(c0.h);
    float2 f1 = __half22float2(c1.h);
    float2 f2 = __half22float2(c2.h);
    float2 f3 = __half22float2(c3.h);
    r0.x += ex * f0.x; r0.y += ex * f0.y; r0.z += ex * f1.x; r0.w += ex * f1.y;
    r1.x += ex * f2.x; r1.y += ex * f2.y; r1.z += ex * f3.x; r1.w += ex * f3.y;
}

__global__ void __launch_bounds__(256) k_agg(float* __restrict__ out) {
    __shared__ float heS[N_ETYPES * NH];
    int t = threadIdx.x;
    if (t < N_ETYPES * NH) heS[t] = g_he[t];
    __syncthreads();
    int warp = t >> 5, lane = t & 31;
    int n = blockIdx.x * 8 + warp;
    if (n >= N_HEAD) return;

    int off = g_offsets[n], end = g_offsets[n + 1];
    float4 r0 = make_float4(0.f, 0.f, 0.f, 0.f);
    float4 r1 = make_float4(0.f, 0.f, 0.f, 0.f);

    if (off != end) {
        float4 hl = *(const float4*)(g_hl + 4 * n);
        int hh = lane >> 3;
        float hlh = hh == 0 ? hl.x : hh == 1 ? hl.y : hh == 2 ? hl.z : hl.w;
        float z = 0.f;

        // process the segment in 32-edge chunks: one coalesced index load per chunk,
        // indices broadcast by shfl -> gather addresses never wait on a load
        for (int base = off; base < end; base += 32) {
            int cnt = end - base; if (cnt > 32) cnt = 32;
            unsigned p = 0;
            if (base + lane < end) p = g_packed[base + lane];

            int j = 0;
            for (; j + 4 <= cnt; j += 4) {
                unsigned p0 = __shfl_sync(~0u, p, j);
                unsigned p1 = __shfl_sync(~0u, p, j + 1);
                unsigned p2 = __shfl_sync(~0u, p, j + 2);
                unsigned p3 = __shfl_sync(~0u, p, j + 3);
                int tt0 = p0 & 0xFFFFF, tt1 = p1 & 0xFFFFF;
                int tt2 = p2 & 0xFFFFF, tt3 = p3 & 0xFFFFF;
                float hr0 = g_hr[4 * tt0 + hh], hr1 = g_hr[4 * tt1 + hh];
                float hr2 = g_hr[4 * tt2 + hh], hr3 = g_hr[4 * tt3 + hh];
                uint4 u0 = *(const uint4*)(g_h_tail + (size_t)tt0 * HD + lane * 8);
                uint4 u1 = *(const uint4*)(g_h_tail + (size_t)tt1 * HD + lane * 8);
                uint4 u2 = *(const uint4*)(g_h_tail + (size_t)tt2 * HD + lane * 8);
                uint4 u3 = *(const uint4*)(g_h_tail + (size_t)tt3 * HD + lane * 8);
                float s0 = hlh + hr0 + heS[(p0 >> 20) * 4 + hh];
                float s1 = hlh + hr1 + heS[(p1 >> 20) * 4 + hh];
                float s2 = hlh + hr2 + heS[(p2 >> 20) * 4 + hh];
                float s3 = hlh + hr3 + heS[(p3 >> 20) * 4 + hh];
                s0 = s0 > 0.f ? s0 : NEG_SLOPE * s0;
                s1 = s1 > 0.f ? s1 : NEG_SLOPE * s1;
                s2 = s2 > 0.f ? s2 : NEG_SLOPE * s2;
                s3 = s3 > 0.f ? s3 : NEG_SLOPE * s3;
                float e0 = __expf(s0), e1 = __expf(s1), e2 = __expf(s2), e3 = __expf(s3);
                z += (e0 + e1) + (e2 + e3);
                acc_edge(e0, u0, r0, r1);
                acc_edge(e1, u1, r0, r1);
                acc_edge(e2, u2, r0, r1);
                acc_edge(e3, u3, r0, r1);
            }
            for (; j < cnt; j++) {
                unsigned pj = __shfl_sync(~0u, p, j);
                int tt = pj & 0xFFFFF;
                float sc = hlh + g_hr[4 * tt + hh] + heS[(pj >> 20) * 4 + hh];
                sc = sc > 0.f ? sc : NEG_SLOPE * sc;
                float ex = __expf(sc);
                z += ex;
                uint4 u = *(const uint4*)(g_h_tail + (size_t)tt * HD + lane * 8);
                acc_edge(ex, u, r0, r1);
            }
        }
        float inv = 1.f / z;
        r0.x *= inv; r0.y *= inv; r0.z *= inv; r0.w *= inv;
        r1.x *= inv; r1.y *= inv; r1.z *= inv; r1.w *= inv;
        r0.x = r0.x > 0.f ? r0.x : __expf(r0.x) - 1.f;
        r0.y = r0.y > 0.f ? r0.y : __expf(r0.y) - 1.f;
        r0.z = r0.z > 0.f ? r0.z : __expf(r0.z) - 1.f;
        r0.w = r0.w > 0.f ? r0.w : __expf(r0.w) - 1.f;
        r1.x = r1.x > 0.f ? r1.x : __expf(r1.x) - 1.f;
        r1.y = r1.y > 0.f ? r1.y : __expf(r1.y) - 1.f;
        r1.z = r1.z > 0.f ? r1.z : __expf(r1.z) - 1.f;
        r1.w = r1.w > 0.f ? r1.w : __expf(r1.w) - 1.f;
    }
    float* op = out + (size_t)n * HD + lane * 8;
    *(float4*)op = r0;
    *((float4*)op + 1) = r1;
}

// ---------------- launch ----------------
extern "C" void kernel_launch(void* const* d_in, const int* in_sizes, int n_in,
                              void* d_out, int out_size) {
    const float* head_feature = (const float*)d_in[0];
    const float* tail_feature = (const float*)d_in[1];
    const int*   edge_list    = (const int*)d_in[2];
    const int*   tmp_edge     = (const int*)d_in[3];
    const float* W            = (const float*)d_in[4];
    const float* W_e          = (const float*)d_in[5];
    const float* edge_emb     = (const float*)d_in[6];
    const float* a_l          = (const float*)d_in[7];
    const float* a_r          = (const float*)d_in[8];
    const float* a_e          = (const float*)d_in[9];
    float* out = (float*)d_out;

    k_prep<<<(N_HEAD + 256) / 256, 256>>>(W, W_e, edge_emb, a_l, a_r, a_e);
    k_hlhr<<<(N_HEAD + 7) / 8, 256>>>(head_feature, tail_feature);
    k_gemm_mma<<<(N_TAIL + GM - 1) / GM, 256>>>(tail_feature, W);
    k_count<<<NE / 256, 256>>>(edge_list);
    k_scan1<<<NSCAN, SCAN_B>>>();
    k_scan2<<<1, 64>>>();
    k_scan3<<<NSCAN, SCAN_B>>>();
    k_scatter<<<NE / 256, 256>>>(edge_list, tmp_edge);
    k_agg<<<(N_HEAD + 7) / 8, 256>>>(out);
}

// round 13
// speedup vs baseline: 1.5840x; 1.5840x over previous
#include <cuda_runtime.h>
#include <cuda_fp16.h>
#include <stdint.h>
#include <math.h>

#define N_HEAD 50000
#define N_TAIL 50000
#define NE     800000
#define F_IN   256
#define DH     64
#define NH     4
#define HD     256   // NH*DH
#define FEW    64
#define N_ETYPES 5
#define NEG_SLOPE 0.2f
#define SCAN_B 1024
#define NSCAN ((N_HEAD + SCAN_B - 1) / SCAN_B)   // 49

// ---------------- device scratch ----------------
__device__ __half g_h_tail[N_TAIL * HD];    // 25.6 MB (fp16)
__device__ float g_hl[N_HEAD * NH];
__device__ float g_hr[N_TAIL * NH];
__device__ float g_Wal[F_IN * NH];
__device__ float g_War[F_IN * NH];
__device__ float g_he[N_ETYPES * NH];
__device__ int   g_counts[N_HEAD + 1];
__device__ int   g_offsets[N_HEAD + 1];
__device__ int   g_cursor[N_HEAD];
__device__ int   g_bsum[NSCAN];
__device__ unsigned g_packed[NE];           // tail | (etype<<20)

// ---------------- prep: zero counters + tiny weight folds ----------------
__global__ void k_prep(const float* __restrict__ W, const float* __restrict__ We,
                       const float* __restrict__ emb, const float* __restrict__ al,
                       const float* __restrict__ ar, const float* __restrict__ ae) {
    int gid = blockIdx.x * blockDim.x + threadIdx.x;
    if (gid <= N_HEAD) g_counts[gid] = 0;
    if (blockIdx.x != 0) return;

    __shared__ float M[FEW * NH];
    int t = threadIdx.x;  // 256
    for (int idx = t; idx < F_IN * NH; idx += 256) {
        int f = idx >> 2, h = idx & 3;
        float sl = 0.f, sr = 0.f;
        #pragma unroll 4
        for (int d = 0; d < DH; d++) {
            float w = W[f * HD + h * DH + d];
            sl += w * al[h * DH + d];
            sr += w * ar[h * DH + d];
        }
        g_Wal[idx] = sl;
        g_War[idx] = sr;
    }
    {
        int k = t >> 2, h = t & 3;
        float s = 0.f;
        #pragma unroll 4
        for (int f = 0; f < FEW; f++) s += ae[h * DH + f] * We[k * (FEW * NH) + h * FEW + f];
        M[t] = s;
    }
    __syncthreads();
    if (t < N_ETYPES * NH) {
        int ty = t >> 2, h = t & 3;
        float s = 0.f;
        #pragma unroll 4
        for (int k = 0; k < FEW; k++) s += emb[ty * FEW + k] * M[k * 4 + h];
        g_he[t] = s;
    }
}

// ---------------- hl / hr : rank-4 projections, warp per node ----------------
__global__ void k_hlhr(const float* __restrict__ hf, const float* __restrict__ tf) {
    __shared__ float sWal[F_IN * NH];
    __shared__ float sWar[F_IN * NH];
    int t = threadIdx.x;
    for (int i = t; i < F_IN * NH; i += 256) { sWal[i] = g_Wal[i]; sWar[i] = g_War[i]; }
    __syncthreads();
    int warp = t >> 5, lane = t & 31;
    int n = blockIdx.x * 8 + warp;
    if (n >= N_HEAD) return;
    int c0 = lane * 8;

    {
        const float4* fr = (const float4*)(hf + (size_t)n * F_IN + c0);
        float4 f0 = fr[0], f1 = fr[1];
        float fv[8] = {f0.x, f0.y, f0.z, f0.w, f1.x, f1.y, f1.z, f1.w};
        float s0 = 0.f, s1 = 0.f, s2 = 0.f, s3 = 0.f;
        #pragma unroll
        for (int j = 0; j < 8; j++) {
            const float* w = &sWal[(c0 + j) * 4];
            s0 += fv[j] * w[0]; s1 += fv[j] * w[1]; s2 += fv[j] * w[2]; s3 += fv[j] * w[3];
        }
        #pragma unroll
        for (int o = 16; o; o >>= 1) {
            s0 += __shfl_xor_sync(~0u, s0, o); s1 += __shfl_xor_sync(~0u, s1, o);
            s2 += __shfl_xor_sync(~0u, s2, o); s3 += __shfl_xor_sync(~0u, s3, o);
        }
        if (lane == 0) *(float4*)(g_hl + 4 * n) = make_float4(s0, s1, s2, s3);
    }
    {
        const float4* fr = (const float4*)(tf + (size_t)n * F_IN + c0);
        float4 f0 = fr[0], f1 = fr[1];
        float fv[8] = {f0.x, f0.y, f0.z, f0.w, f1.x, f1.y, f1.z, f1.w};
        float s0 = 0.f, s1 = 0.f, s2 = 0.f, s3 = 0.f;
        #pragma unroll
        for (int j = 0; j < 8; j++) {
            const float* w = &sWar[(c0 + j) * 4];
            s0 += fv[j] * w[0]; s1 += fv[j] * w[1]; s2 += fv[j] * w[2]; s3 += fv[j] * w[3];
        }
        #pragma unroll
        for (int o = 16; o; o >>= 1) {
            s0 += __shfl_xor_sync(~0u, s0, o); s1 += __shfl_xor_sync(~0u, s1, o);
            s2 += __shfl_xor_sync(~0u, s2, o); s3 += __shfl_xor_sync(~0u, s3, o);
        }
        if (lane == 0) *(float4*)(g_hr + 4 * n) = make_float4(s0, s1, s2, s3);
    }
}

// ---------------- GEMM via HMMA: g_h_tail = fp16(tail_feature @ W) ----------------
#define GM 64
#define APAD 24
#define BPAD 264

__device__ __forceinline__ uint32_t smem_u32(const void* p) {
    return (uint32_t)__cvta_generic_to_shared(p);
}

__global__ void __launch_bounds__(256) k_gemm_mma(const float* __restrict__ A,
                                                  const float* __restrict__ B) {
    __shared__ __half As[2][GM][APAD];
    __shared__ __half Bs[2][16][BPAD];
    int t = threadIdx.x;
    int warp = t >> 5, lane = t & 31;
    int m0 = blockIdx.x * GM;
    int warp_m = (warp & 1) * 32;
    int warp_n = (warp >> 1) * 64;

    float acc[2][8][4];
    #pragma unroll
    for (int i = 0; i < 2; i++)
        #pragma unroll
        for (int j = 0; j < 8; j++)
            #pragma unroll
            for (int k = 0; k < 4; k++) acc[i][j][k] = 0.f;

    auto load_tile = [&](int buf, int k0) {
        {
            int row = t >> 2, kc = (t & 3) * 4;
            float4 a = (m0 + row < N_TAIL)
                ? *(const float4*)(A + (size_t)(m0 + row) * F_IN + k0 + kc)
                : make_float4(0.f, 0.f, 0.f, 0.f);
            __half2* dst = (__half2*)&As[buf][row][kc];
            dst[0] = __floats2half2_rn(a.x, a.y);
            dst[1] = __floats2half2_rn(a.z, a.w);
        }
        #pragma unroll
        for (int j = 0; j < 4; j++) {
            int idx = t + j * 256;
            int br = idx >> 6, bc = (idx & 63) * 4;
            float4 b = *(const float4*)(B + (size_t)(k0 + br) * HD + bc);
            __half2* dst = (__half2*)&Bs[buf][br][bc];
            dst[0] = __floats2half2_rn(b.x, b.y);
            dst[1] = __floats2half2_rn(b.z, b.w);
        }
    };

    load_tile(0, 0);
    __syncthreads();

    int lm_r = lane & 15;
    int lm_c = (lane >> 4) * 8;

    for (int kc = 0; kc < F_IN / 16; kc++) {
        int buf = kc & 1;
        if (kc < F_IN / 16 - 1) load_tile(buf ^ 1, (kc + 1) * 16);

        uint32_t afr[2][4];
        #pragma unroll
        for (int mt = 0; mt < 2; mt++) {
            uint32_t addr = smem_u32(&As[buf][warp_m + mt * 16 + lm_r][lm_c]);
            asm volatile("ldmatrix.sync.aligned.m8n8.x4.shared.b16 {%0,%1,%2,%3},[%4];"
                         : "=r"(afr[mt][0]), "=r"(afr[mt][1]), "=r"(afr[mt][2]), "=r"(afr[mt][3])
                         : "r"(addr));
        }
        uint32_t bfr[4][4];
        #pragma unroll
        for (int ng = 0; ng < 4; ng++) {
            uint32_t addr = smem_u32(&Bs[buf][lm_r][warp_n + ng * 16 + lm_c]);
            asm volatile("ldmatrix.sync.aligned.m8n8.x4.trans.shared.b16 {%0,%1,%2,%3},[%4];"
                         : "=r"(bfr[ng][0]), "=r"(bfr[ng][1]), "=r"(bfr[ng][2]), "=r"(bfr[ng][3])
                         : "r"(addr));
        }
        #pragma unroll
        for (int mt = 0; mt < 2; mt++) {
            #pragma unroll
            for (int nt = 0; nt < 8; nt++) {
                uint32_t b0 = bfr[nt >> 1][(nt & 1) * 2];
                uint32_t b1 = bfr[nt >> 1][(nt & 1) * 2 + 1];
                asm volatile(
                    "mma.sync.aligned.m16n8k16.row.col.f32.f16.f16.f32 "
                    "{%0,%1,%2,%3},{%4,%5,%6,%7},{%8,%9},{%0,%1,%2,%3};"
                    : "+f"(acc[mt][nt][0]), "+f"(acc[mt][nt][1]),
                      "+f"(acc[mt][nt][2]), "+f"(acc[mt][nt][3])
                    : "r"(afr[mt][0]), "r"(afr[mt][1]), "r"(afr[mt][2]), "r"(afr[mt][3]),
                      "r"(b0), "r"(b1));
            }
        }
        __syncthreads();
    }

    int rbase = m0 + warp_m + (lane >> 2);
    int cbase = warp_n + (lane & 3) * 2;
    #pragma unroll
    for (int mt = 0; mt < 2; mt++) {
        int r0 = rbase + mt * 16;
        #pragma unroll
        for (int nt = 0; nt < 8; nt++) {
            int c = cbase + nt * 8;
            if (r0 < N_TAIL)
                *(__half2*)(g_h_tail + (size_t)r0 * HD + c) =
                    __floats2half2_rn(acc[mt][nt][0], acc[mt][nt][1]);
            if (r0 + 8 < N_TAIL)
                *(__half2*)(g_h_tail + (size_t)(r0 + 8) * HD + c) =
                    __floats2half2_rn(acc[mt][nt][2], acc[mt][nt][3]);
        }
    }
}

// ---------------- CSR build ----------------
__global__ void k_count(const int* __restrict__ edge_list) {
    int i = blockIdx.x * blockDim.x + threadIdx.x;
    if (i < NE) atomicAdd(&g_counts[edge_list[i]], 1);
}

__global__ void k_scan1() {
    __shared__ int warp_sums[32];
    int t = threadIdx.x, b = blockIdx.x;
    int idx = b * SCAN_B + t;
    int x = (idx < N_HEAD) ? g_counts[idx] : 0;
    int v = x;
    #pragma unroll
    for (int o = 1; o < 32; o <<= 1) {
        int u = __shfl_up_sync(~0u, v, o);
        if ((t & 31) >= o) v += u;
    }
    if ((t & 31) == 31) warp_sums[t >> 5] = v;
    __syncthreads();
    if (t < 32) {
        int w = warp_sums[t];
        #pragma unroll
        for (int o = 1; o < 32; o <<= 1) {
            int u = __shfl_up_sync(~0u, w, o);
            if (t >= o) w += u;
        }
        warp_sums[t] = w;
    }
    __syncthreads();
    int incl = v + ((t >= 32) ? warp_sums[(t >> 5) - 1] : 0);
    if (idx < N_HEAD) g_offsets[idx] = incl - x;
    if (t == SCAN_B - 1) g_bsum[b] = incl;
}

__global__ void k_scan2() {
    __shared__ int wsum[2];
    int t = threadIdx.x;  // 64
    int v = (t < NSCAN) ? g_bsum[t] : 0;
    int x = v;
    #pragma unroll
    for (int o = 1; o < 32; o <<= 1) {
        int u = __shfl_up_sync(~0u, x, o);
        if ((t & 31) >= o) x += u;
    }
    if ((t & 31) == 31) wsum[t >> 5] = x;
    __syncthreads();
    if (t >= 32) x += wsum[0];
    if (t < NSCAN) g_bsum[t] = x - v;
}

__global__ void k_scan3() {
    int t = threadIdx.x, b = blockIdx.x;
    int idx = b * SCAN_B + t;
    if (idx < N_HEAD) {
        int o = g_offsets[idx] + g_bsum[b];
        g_offsets[idx] = o;
        g_cursor[idx] = o;
    }
    if (idx == 0) g_offsets[N_HEAD] = NE;
}

__global__ void k_scatter(const int* __restrict__ edge_list, const int* __restrict__ tmp_edge) {
    int i = blockIdx.x * blockDim.x + threadIdx.x;
    if (i >= NE) return;
    int h  = edge_list[i];
    int tt = edge_list[NE + i];
    int ty = tmp_edge[i];
    int pos = atomicAdd(&g_cursor[h], 1);
    g_packed[pos] = (unsigned)tt | ((unsigned)ty << 20);
}

// ---------------- aggregation: warp per node, index-prefetch pipeline ----------------
__device__ __forceinline__ void acc_edge(float ex, uint4 u, float4& r0, float4& r1) {
    union { unsigned u; __half2 h; } c0, c1, c2, c3;
    c0.u = u.x; c1.u = u.y; c2.u = u.z; c3.u = u.w;
    float2 f0 = __half22float2(c0.h);
    float2 f1 = __half22float2(c1.h);
    float2 f2 = __half22float2(c2.h);
    float2 f3 = __half22float2(c3.h);
    r0.x += ex * f0.x; r0.y += ex * f0.y; r0.z += ex * f1.x; r0.w += ex * f1.y;
    r1.x += ex * f2.x; r1.y += ex * f2.y; r1.z += ex * f3.x; r1.w += ex * f3.y;
}

__global__ void __launch_bounds__(256) k_agg(float* __restrict__ out) {
    __shared__ float heS[N_ETYPES * NH];
    int t = threadIdx.x;
    if (t < N_ETYPES * NH) heS[t] = g_he[t];
    __syncthreads();
    int warp = t >> 5, lane = t & 31;
    int n = blockIdx.x * 8 + warp;
    if (n >= N_HEAD) return;

    int off = g_offsets[n], end = g_offsets[n + 1];
    float4 r0 = make_float4(0.f, 0.f, 0.f, 0.f);
    float4 r1 = make_float4(0.f, 0.f, 0.f, 0.f);

    if (off != end) {
        float4 hl = *(const float4*)(g_hl + 4 * n);
        int hh = lane >> 3;
        float hlh = hh == 0 ? hl.x : hh == 1 ? hl.y : hh == 2 ? hl.z : hl.w;
        float z = 0.f;
        int i = off;

        // 4-edge groups with next-group index prefetch
        unsigned q0 = 0, q1 = 0, q2 = 0, q3 = 0;
        bool haveq = (i + 4 <= end);
        if (haveq) {
            q0 = g_packed[i];     q1 = g_packed[i + 1];
            q2 = g_packed[i + 2]; q3 = g_packed[i + 3];
        }
        for (; i + 8 <= end; i += 4) {
            unsigned p0 = q0, p1 = q1, p2 = q2, p3 = q3;
            q0 = g_packed[i + 4]; q1 = g_packed[i + 5];
            q2 = g_packed[i + 6]; q3 = g_packed[i + 7];
            int tt0 = p0 & 0xFFFFF, tt1 = p1 & 0xFFFFF;
            int tt2 = p2 & 0xFFFFF, tt3 = p3 & 0xFFFFF;
            float hr0 = g_hr[4 * tt0 + hh], hr1 = g_hr[4 * tt1 + hh];
            float hr2 = g_hr[4 * tt2 + hh], hr3 = g_hr[4 * tt3 + hh];
            uint4 u0 = *(const uint4*)(g_h_tail + (size_t)tt0 * HD + lane * 8);
            uint4 u1 = *(const uint4*)(g_h_tail + (size_t)tt1 * HD + lane * 8);
            uint4 u2 = *(const uint4*)(g_h_tail + (size_t)tt2 * HD + lane * 8);
            uint4 u3 = *(const uint4*)(g_h_tail + (size_t)tt3 * HD + lane * 8);
            float s0 = hlh + hr0 + heS[(p0 >> 20) * 4 + hh];
            float s1 = hlh + hr1 + heS[(p1 >> 20) * 4 + hh];
            float s2 = hlh + hr2 + heS[(p2 >> 20) * 4 + hh];
            float s3 = hlh + hr3 + heS[(p3 >> 20) * 4 + hh];
            s0 = s0 > 0.f ? s0 : NEG_SLOPE * s0;
            s1 = s1 > 0.f ? s1 : NEG_SLOPE * s1;
            s2 = s2 > 0.f ? s2 : NEG_SLOPE * s2;
            s3 = s3 > 0.f ? s3 : NEG_SLOPE * s3;
            float e0 = __expf(s0), e1 = __expf(s1), e2 = __expf(s2), e3 = __expf(s3);
            z += (e0 + e1) + (e2 + e3);
            acc_edge(e0, u0, r0, r1);
            acc_edge(e1, u1, r0, r1);
            acc_edge(e2, u2, r0, r1);
            acc_edge(e3, u3, r0, r1);
        }
        if (haveq) {
            // process the last prefetched group
            int tt0 = q0 & 0xFFFFF, tt1 = q1 & 0xFFFFF;
            int tt2 = q2 & 0xFFFFF, tt3 = q3 & 0xFFFFF;
            float hr0 = g_hr[4 * tt0 + hh], hr1 = g_hr[4 * tt1 + hh];
            float hr2 = g_hr[4 * tt2 + hh], hr3 = g_hr[4 * tt3 + hh];
            uint4 u0 = *(const uint4*)(g_h_tail + (size_t)tt0 * HD + lane * 8);
            uint4 u1 = *(const uint4*)(g_h_tail + (size_t)tt1 * HD + lane * 8);
            uint4 u2 = *(const uint4*)(g_h_tail + (size_t)tt2 * HD + lane * 8);
            uint4 u3 = *(const uint4*)(g_h_tail + (size_t)tt3 * HD + lane * 8);
            float s0 = hlh + hr0 + heS[(q0 >> 20) * 4 + hh];
            float s1 = hlh + hr1 + heS[(q1 >> 20) * 4 + hh];
            float s2 = hlh + hr2 + heS[(q2 >> 20) * 4 + hh];
            float s3 = hlh + hr3 + heS[(q3 >> 20) * 4 + hh];
            s0 = s0 > 0.f ? s0 : NEG_SLOPE * s0;
            s1 = s1 > 0.f ? s1 : NEG_SLOPE * s1;
            s2 = s2 > 0.f ? s2 : NEG_SLOPE * s2;
            s3 = s3 > 0.f ? s3 : NEG_SLOPE * s3;
            float e0 = __expf(s0), e1 = __expf(s1), e2 = __expf(s2), e3 = __expf(s3);
            z += (e0 + e1) + (e2 + e3);
            acc_edge(e0, u0, r0, r1);
            acc_edge(e1, u1, r0, r1);
            acc_edge(e2, u2, r0, r1);
            acc_edge(e3, u3, r0, r1);
            i += 4;
        }
        for (; i < end; i++) {
            unsigned p = g_packed[i];
            int tt = p & 0xFFFFF;
            float sc = hlh + g_hr[4 * tt + hh] + heS[(p >> 20) * 4 + hh];
            sc = sc > 0.f ? sc : NEG_SLOPE * sc;
            float ex = __expf(sc);
            z += ex;
            uint4 u = *(const uint4*)(g_h_tail + (size_t)tt * HD + lane * 8);
            acc_edge(ex, u, r0, r1);
        }
        float inv = 1.f / z;
        r0.x *= inv; r0.y *= inv; r0.z *= inv; r0.w *= inv;
        r1.x *= inv; r1.y *= inv; r1.z *= inv; r1.w *= inv;
        r0.x = r0.x > 0.f ? r0.x : __expf(r0.x) - 1.f;
        r0.y = r0.y > 0.f ? r0.y : __expf(r0.y) - 1.f;
        r0.z = r0.z > 0.f ? r0.z : __expf(r0.z) - 1.f;
        r0.w = r0.w > 0.f ? r0.w : __expf(r0.w) - 1.f;
        r1.x = r1.x > 0.f ? r1.x : __expf(r1.x) - 1.f;
        r1.y = r1.y > 0.f ? r1.y : __expf(r1.y) - 1.f;
        r1.z = r1.z > 0.f ? r1.z : __expf(r1.z) - 1.f;
        r1.w = r1.w > 0.f ? r1.w : __expf(r1.w) - 1.f;
    }
    float* op = out + (size_t)n * HD + lane * 8;
    *(float4*)op = r0;
    *((float4*)op + 1) = r1;
}

// ---------------- launch ----------------
extern "C" void kernel_launch(void* const* d_in, const int* in_sizes, int n_in,
                              void* d_out, int out_size) {
    const float* head_feature = (const float*)d_in[0];
    const float* tail_feature = (const float*)d_in[1];
    const int*   edge_list    = (const int*)d_in[2];
    const int*   tmp_edge     = (const int*)d_in[3];
    const float* W            = (const float*)d_in[4];
    const float* W_e          = (const float*)d_in[5];
    const float* edge_emb     = (const float*)d_in[6];
    const float* a_l          = (const float*)d_in[7];
    const float* a_r          = (const float*)d_in[8];
    const float* a_e          = (const float*)d_in[9];
    float* out = (float*)d_out;

    k_prep<<<(N_HEAD + 256) / 256, 256>>>(W, W_e, edge_emb, a_l, a_r, a_e);
    k_hlhr<<<(N_HEAD + 7) / 8, 256>>>(head_feature, tail_feature);
    k_gemm_mma<<<(N_TAIL + GM - 1) / GM, 256>>>(tail_feature, W);
    k_count<<<NE / 256, 256>>>(edge_list);
    k_scan1<<<NSCAN, SCAN_B>>>();
    k_scan2<<<1, 64>>>();
    k_scan3<<<NSCAN, SCAN_B>>>();
    k_scatter<<<NE / 256, 256>>>(edge_list, tmp_edge);
    k_agg<<<(N_HEAD + 7) / 8, 256>>>(out);
}